// round 1
// baseline (speedup 1.0000x reference)
#include <cuda_runtime.h>
#include <cuda_fp16.h>
#include <cstdint>

#define NB    8192
#define PTS   128
#define HID   128
#define CCH   32
#define LATD  16

#define SH    136    // padded half stride for h1/h2/W2t/W3t rows
#define ZST   129    // padded float stride for z-transposed rows
#define XST   24     // padded half stride for xh / W1t rows (K=16 padded)

// shared memory byte offsets (16B aligned)
#define OFF_XRAW   0        // 2*512*4   = 4096
#define OFF_EPS    4096     // 2*16*4    = 128
#define OFF_XH     4224     // 128*24*2  = 6144
#define OFF_W1T    10368    // 128*24*2  = 6144
#define OFF_B1     16512    // 512
#define OFF_B2     17024    // 512
#define OFF_B3     17536    // 128
#define OFF_POOLED 17664    // 128
#define OFF_W2T    17792    // 128*136*2 = 34816
#define OFF_W3T    52608    // 32*136*2  = 8704
#define OFF_H1     61312    // 34816
#define OFF_H2     96128    // 34816
#define OFF_ZT     130944   // 32*129*4  = 16512
#define OFF_WPOOL  147456   // 32*128*4  = 16384
#define SMEM_BYTES 163840

__device__ __forceinline__ void mma16816(float* d, const uint32_t* a, const uint32_t* b) {
    asm volatile(
        "mma.sync.aligned.m16n8k16.row.col.f32.f16.f16.f32 "
        "{%0,%1,%2,%3},{%4,%5,%6,%7},{%8,%9},{%0,%1,%2,%3};\n"
        : "+f"(d[0]), "+f"(d[1]), "+f"(d[2]), "+f"(d[3])
        : "r"(a[0]), "r"(a[1]), "r"(a[2]), "r"(a[3]), "r"(b[0]), "r"(b[1]));
}

__device__ __forceinline__ void cp16(void* s, const void* g) {
    uint32_t sa = (uint32_t)__cvta_generic_to_shared(s);
    asm volatile("cp.async.ca.shared.global [%0], [%1], 16;\n" :: "r"(sa), "l"(g));
}

// Warp-tiled GEMM: C[128 x 128] = relu(A[128 x K] * B^T + bias), fp16 in/out, fp32 acc.
// 16 warps, each a 32x32 tile. A rows: M(points) x K, B rows: N x K (both k-contiguous).
template<int KSTEPS, int ASTR, int BSTR>
__device__ __forceinline__ void gemm_relu(const __half* A, const __half* Bm,
                                          const float* bias, __half* C,
                                          int w, int lane) {
    const int g = lane >> 2, t = lane & 3;
    const int wm = (w & 3) * 32, wn = (w >> 2) * 32;
    float acc[32];
#pragma unroll
    for (int i = 0; i < 32; i++) acc[i] = 0.f;
#pragma unroll
    for (int ks = 0; ks < KSTEPS; ks++) {
        const int k0 = ks * 16;
        uint32_t a[2][4], bf[4][2];
#pragma unroll
        for (int ms = 0; ms < 2; ms++) {
            const __half* ap = A + (wm + 16 * ms + g) * ASTR + k0 + 2 * t;
            a[ms][0] = *(const uint32_t*)(ap);
            a[ms][1] = *(const uint32_t*)(ap + 8 * ASTR);
            a[ms][2] = *(const uint32_t*)(ap + 8);
            a[ms][3] = *(const uint32_t*)(ap + 8 * ASTR + 8);
        }
#pragma unroll
        for (int nt = 0; nt < 4; nt++) {
            const __half* bp = Bm + (wn + 8 * nt + g) * BSTR + k0 + 2 * t;
            bf[nt][0] = *(const uint32_t*)(bp);
            bf[nt][1] = *(const uint32_t*)(bp + 8);
        }
#pragma unroll
        for (int ms = 0; ms < 2; ms++)
#pragma unroll
            for (int nt = 0; nt < 4; nt++)
                mma16816(&acc[(ms * 4 + nt) * 4], a[ms], bf[nt]);
    }
    // epilogue: bias + relu -> fp16
#pragma unroll
    for (int ms = 0; ms < 2; ms++)
#pragma unroll
        for (int nt = 0; nt < 4; nt++) {
            const int r0 = wm + 16 * ms + g;
            const int c0 = wn + 8 * nt + 2 * t;
            const float* a = &acc[(ms * 4 + nt) * 4];
            float bb0 = bias[c0], bb1 = bias[c0 + 1];
            __half2 lo = __floats2half2_rn(fmaxf(a[0] + bb0, 0.f), fmaxf(a[1] + bb1, 0.f));
            __half2 hi = __floats2half2_rn(fmaxf(a[2] + bb0, 0.f), fmaxf(a[3] + bb1, 0.f));
            *(__half2*)(C + r0 * SH + c0) = lo;
            *(__half2*)(C + (r0 + 8) * SH + c0) = hi;
        }
}

__global__ void __launch_bounds__(512, 1)
enc_kernel(const float* __restrict__ x,  const float* __restrict__ W1,
           const float* __restrict__ b1, const float* __restrict__ W2,
           const float* __restrict__ b2, const float* __restrict__ W3,
           const float* __restrict__ b3, const float* __restrict__ pw,
           const float* __restrict__ eps, float* __restrict__ out) {
    extern __shared__ char smem[];
    float*  xraw  = (float*)(smem + OFF_XRAW);
    float*  epsb  = (float*)(smem + OFF_EPS);
    __half* xh    = (__half*)(smem + OFF_XH);
    __half* W1t   = (__half*)(smem + OFF_W1T);
    float*  b1s   = (float*)(smem + OFF_B1);
    float*  b2s   = (float*)(smem + OFF_B2);
    float*  b3s   = (float*)(smem + OFF_B3);
    float*  pooled= (float*)(smem + OFF_POOLED);
    __half* W2t   = (__half*)(smem + OFF_W2T);
    __half* W3t   = (__half*)(smem + OFF_W3T);
    __half* h1    = (__half*)(smem + OFF_H1);
    __half* h2    = (__half*)(smem + OFF_H2);
    float*  zt    = (float*)(smem + OFF_ZT);
    float*  wpool = (float*)(smem + OFF_WPOOL);

    const int tid  = threadIdx.x;
    const int w    = tid >> 5;
    const int lane = tid & 31;
    const int g    = lane >> 2, t = lane & 3;

    // ---------------- prologue (once per CTA) ----------------
    // zero xh + W1t (contiguous 12288B) so K-padding (k=4..15) is zero
    for (int i = tid; i < 3072; i += 512) ((uint32_t*)(smem + OFF_XH))[i] = 0;
    __syncthreads();
    // W1t[h][f] = W1[f][h]  (fp16)
    { int f = tid >> 7, h = tid & 127; W1t[h * XST + f] = __float2half(W1[tid]); }
    if (tid < 128) { b1s[tid] = b1[tid]; b2s[tid] = b2[tid]; }
    if (tid < 32)  b3s[tid] = b3[tid];
    for (int i = tid; i < 16384; i += 512) {            // W2t[n][k] = W2[k][n]
        int k = i >> 7, n = i & 127;
        W2t[n * SH + k] = __float2half(W2[i]);
    }
    for (int i = tid; i < 4096; i += 512) {             // W3t[n][k] = W3[k][n]
        int k = i >> 5, n = i & 31;
        W3t[n * SH + k] = __float2half(W3[i]);
    }
    for (int i = tid; i < 4096; i += 512) {             // FSPool weights
        int c = i >> 7, p = i & 127;
        float pos = ((float)p / 127.0f) * 20.0f;
        int idx = (int)pos; if (idx > 20) idx = 20;
        float frac = pos - (float)idx;
        int idx2 = idx + 1; if (idx2 > 20) idx2 = 20;
        wpool[i] = (1.0f - frac) * pw[c * 21 + idx] + frac * pw[c * 21 + idx2];
    }
    // prefetch first batch into buffer 0
    {
        int b0 = blockIdx.x;
        if (tid < 128)      cp16(xraw + tid * 4, x + (size_t)b0 * 512 + tid * 4);
        else if (tid < 132) cp16(epsb + (tid - 128) * 4, eps + (size_t)b0 * 16 + (tid - 128) * 4);
    }
    asm volatile("cp.async.commit_group;\n");

    int buf = 0;
    const int grid = gridDim.x;

    for (int b = blockIdx.x; b < NB; b += grid) {
        // prefetch next batch into other buffer
        int bn = b + grid; if (bn >= NB) bn = blockIdx.x;
        int nb = buf ^ 1;
        if (tid < 128)      cp16(xraw + nb * 512 + tid * 4, x + (size_t)bn * 512 + tid * 4);
        else if (tid < 132) cp16(epsb + nb * 16 + (tid - 128) * 4, eps + (size_t)bn * 16 + (tid - 128) * 4);
        asm volatile("cp.async.commit_group;\n");
        asm volatile("cp.async.wait_group 1;\n");
        __syncthreads();

        // A: convert x (fp32) -> xh (fp16, K padded with zeros)
        { int p = tid >> 2, f = tid & 3; xh[p * XST + f] = __float2half(xraw[buf * 512 + tid]); }
        __syncthreads();

        // B: layer1  h1 = relu(x @ W1 + b1)   (M=128,N=128,K=16 padded)
        gemm_relu<1, XST, XST>(xh, W1t, b1s, h1, w, lane);
        __syncthreads();

        // C: layer2  h2 = relu(h1 @ W2 + b2)  (K=128)
        gemm_relu<8, SH, SH>(h1, W2t, b2s, h2, w, lane);
        __syncthreads();

        // D: layer3  z^T[c][p] = h2 @ W3 + b3  (N=32) -> fp32, channel-major
        {
            const int wm = (w & 3) * 32, wn = (w >> 2) * 8;
            float acc[2][4];
#pragma unroll
            for (int ms = 0; ms < 2; ms++)
#pragma unroll
                for (int i = 0; i < 4; i++) acc[ms][i] = 0.f;
#pragma unroll
            for (int ks = 0; ks < 8; ks++) {
                const int k0 = ks * 16;
                uint32_t a[2][4], bf[2];
#pragma unroll
                for (int ms = 0; ms < 2; ms++) {
                    const __half* ap = h2 + (wm + 16 * ms + g) * SH + k0 + 2 * t;
                    a[ms][0] = *(const uint32_t*)(ap);
                    a[ms][1] = *(const uint32_t*)(ap + 8 * SH);
                    a[ms][2] = *(const uint32_t*)(ap + 8);
                    a[ms][3] = *(const uint32_t*)(ap + 8 * SH + 8);
                }
                const __half* bp = W3t + (wn + g) * SH + k0 + 2 * t;
                bf[0] = *(const uint32_t*)(bp);
                bf[1] = *(const uint32_t*)(bp + 8);
                mma16816(acc[0], a[0], bf);
                mma16816(acc[1], a[1], bf);
            }
#pragma unroll
            for (int ms = 0; ms < 2; ms++) {
                const int r = wm + 16 * ms + g;
                const int c = wn + 2 * t;
                zt[c * ZST + r]           = acc[ms][0] + b3s[c];
                zt[(c + 1) * ZST + r]     = acc[ms][1] + b3s[c + 1];
                zt[c * ZST + r + 8]       = acc[ms][2] + b3s[c];
                zt[(c + 1) * ZST + r + 8] = acc[ms][3] + b3s[c + 1];
            }
        }
        __syncthreads();

        // E: per-warp register bitonic sort (descending) + weighted pool, 2 channels/warp
        for (int ci = 0; ci < 2; ci++) {
            const int c = w * 2 + ci;
            float v[4];
#pragma unroll
            for (int j = 0; j < 4; j++) v[j] = zt[c * ZST + lane + 32 * j];
#pragma unroll
            for (int k = 2; k <= 128; k <<= 1) {
#pragma unroll
                for (int d = k >> 1; d > 0; d >>= 1) {
                    if (d >= 32) {
                        const int dj = d >> 5;
#pragma unroll
                        for (int j = 0; j < 4; j++) {
                            if ((j & dj) == 0) {
                                const int j2 = j | dj;
                                const int e = lane + 32 * j;
                                const bool desc = ((e & k) == 0);
                                float lo = fminf(v[j], v[j2]);
                                float hi = fmaxf(v[j], v[j2]);
                                v[j]  = desc ? hi : lo;
                                v[j2] = desc ? lo : hi;
                            }
                        }
                    } else {
#pragma unroll
                        for (int j = 0; j < 4; j++) {
                            const int e = lane + 32 * j;
                            float pv = __shfl_xor_sync(0xffffffffu, v[j], d);
                            const bool keepmax = (((e & k) == 0) == ((lane & d) == 0));
                            v[j] = keepmax ? fmaxf(v[j], pv) : fminf(v[j], pv);
                        }
                    }
                }
            }
            float s = 0.f;
#pragma unroll
            for (int j = 0; j < 4; j++) s += v[j] * wpool[c * 128 + lane + 32 * j];
#pragma unroll
            for (int o = 16; o > 0; o >>= 1) s += __shfl_down_sync(0xffffffffu, s, o);
            if (lane == 0) pooled[c] = s;
        }
        __syncthreads();

        // F: outputs (mus | logvars | samples concatenated)
        if (tid < LATD) {
            const int l = tid;
            float mu = pooled[2 * l];
            float lv = pooled[2 * l + 1];
            float ev = epsb[buf * 16 + l];
            float sp = mu + ev * expf(0.5f * lv);
            out[(size_t)b * 16 + l]                         = mu;
            out[(size_t)NB * 16 + (size_t)b * 16 + l]       = lv;
            out[(size_t)2 * NB * 16 + (size_t)b * 16 + l]   = sp;
        }
        __syncthreads();   // protect eps/pooled before next iteration's prefetch
        buf ^= 1;
    }
}

extern "C" void kernel_launch(void* const* d_in, const int* in_sizes, int n_in,
                              void* d_out, int out_size) {
    const float* x   = (const float*)d_in[0];
    const float* W1  = (const float*)d_in[1];
    const float* b1  = (const float*)d_in[2];
    const float* W2  = (const float*)d_in[3];
    const float* b2  = (const float*)d_in[4];
    const float* W3  = (const float*)d_in[5];
    const float* b3  = (const float*)d_in[6];
    const float* pw  = (const float*)d_in[7];
    const float* eps = (const float*)d_in[8];
    float* out = (float*)d_out;

    int dev = 0;
    cudaGetDevice(&dev);
    int nsm = 148;
    cudaDeviceGetAttribute(&nsm, cudaDevAttrMultiProcessorCount, dev);
    cudaFuncSetAttribute(enc_kernel, cudaFuncAttributeMaxDynamicSharedMemorySize, SMEM_BYTES);
    enc_kernel<<<nsm, 512, SMEM_BYTES>>>(x, W1, b1, W2, b2, W3, b3, pw, eps, out);
}

// round 2
// speedup vs baseline: 1.2559x; 1.2559x over previous
#include <cuda_runtime.h>
#include <cuda_fp16.h>
#include <cstdint>

#define NB    8192
#define SH    136    // padded half stride for h1/h2/W2t/W3t rows (68 words -> conflict-free)
#define ZST   132    // padded float stride for zt rows (16B aligned, conflict-free stores+float4 loads)

// shared memory byte offsets (16B aligned)
#define OFF_XRAW   0        // 2*512*4 = 4096
#define OFF_EPS    4096     // 2*16*4  = 128
#define OFF_B1     4224     // 512
#define OFF_B2     4736     // 512
#define OFF_B3     5248     // 128
#define OFF_POOLED 5376     // 128
#define OFF_W3T    5504     // 32*136*2 = 8704
#define OFF_H1     14208    // 128*136*2 = 34816   (W2 staged here in prologue)
#define OFF_H2     49024    // 128*136*2 = 34816   (unused in prologue)
#define OFF_ZT     83840    // 32*132*4 = 16896
#define SMEM_BYTES 100736

__device__ __forceinline__ void mma16816(float* d, const uint32_t* a, const uint32_t* b) {
    asm volatile(
        "mma.sync.aligned.m16n8k16.row.col.f32.f16.f16.f32 "
        "{%0,%1,%2,%3},{%4,%5,%6,%7},{%8,%9},{%0,%1,%2,%3};\n"
        : "+f"(d[0]), "+f"(d[1]), "+f"(d[2]), "+f"(d[3])
        : "r"(a[0]), "r"(a[1]), "r"(a[2]), "r"(a[3]), "r"(b[0]), "r"(b[1]));
}

__device__ __forceinline__ void mma16808(float* d, const uint32_t* a, uint32_t b) {
    asm volatile(
        "mma.sync.aligned.m16n8k8.row.col.f32.f16.f16.f32 "
        "{%0,%1,%2,%3},{%4,%5},{%6},{%0,%1,%2,%3};\n"
        : "+f"(d[0]), "+f"(d[1]), "+f"(d[2]), "+f"(d[3])
        : "r"(a[0]), "r"(a[1]), "r"(b));
}

#define LDSM4(r, addr) \
    asm volatile("ldmatrix.sync.aligned.m8n8.x4.shared.b16 {%0,%1,%2,%3}, [%4];" \
                 : "=r"((r)[0]), "=r"((r)[1]), "=r"((r)[2]), "=r"((r)[3]) : "r"(addr))

__device__ __forceinline__ void cp16(void* s, const void* g) {
    uint32_t sa = (uint32_t)__cvta_generic_to_shared(s);
    asm volatile("cp.async.ca.shared.global [%0], [%1], 16;\n" :: "r"(sa), "l"(g));
}

__device__ __forceinline__ uint32_t packh2(float a, float b) {
    __half2 h = __floats2half2_rn(a, b);
    return *(uint32_t*)&h;
}

#define CEX(a, b, dsc) do { float _hi = fmaxf(a, b), _lo = fminf(a, b); \
                            (a) = (dsc) ? _hi : _lo; (b) = (dsc) ? _lo : _hi; } while (0)

__global__ void __launch_bounds__(256, 1)
enc_kernel(const float* __restrict__ x,  const float* __restrict__ W1,
           const float* __restrict__ b1, const float* __restrict__ W2,
           const float* __restrict__ b2, const float* __restrict__ W3,
           const float* __restrict__ b3, const float* __restrict__ pw,
           const float* __restrict__ eps, float* __restrict__ out) {
    extern __shared__ char smem[];
    float*  xraw  = (float*)(smem + OFF_XRAW);
    float*  epsb  = (float*)(smem + OFF_EPS);
    float*  b1s   = (float*)(smem + OFF_B1);
    float*  b2s   = (float*)(smem + OFF_B2);
    float*  b3s   = (float*)(smem + OFF_B3);
    float*  pooled= (float*)(smem + OFF_POOLED);
    __half* W3t   = (__half*)(smem + OFF_W3T);
    __half* h1    = (__half*)(smem + OFF_H1);
    __half* h2    = (__half*)(smem + OFF_H2);
    float*  zt    = (float*)(smem + OFF_ZT);

    const int tid  = threadIdx.x;
    const int w    = tid >> 5;
    const int lane = tid & 31;
    const int g    = lane >> 2, t = lane & 3;

    // warp tiles
    const int wm12 = (w & 1) * 64, wn12 = (w >> 1) * 32;   // layers 1,2: 64x32
    const int wm3  = (w & 3) * 32, wn3  = (w >> 2) * 16;   // layer 3: 32x16

    // ldmatrix lane address components
    const int mi    = lane >> 3;
    const int arow  = (mi & 1) * 8 + (lane & 7);
    const int acol  = (mi >> 1) * 8;

    const uint32_t smem_u32 = (uint32_t)__cvta_generic_to_shared(smem);
    const uint32_t aBase2 = smem_u32 + OFF_H1 + ((wm12 + arow) * SH + acol) * 2;
    const uint32_t aBase3 = smem_u32 + OFF_H2 + ((wm3  + arow) * SH + acol) * 2;

    // ---------------- prologue ----------------
    // stage W2 transposed into h1 region (reused after), W3 into its own region
    __half* W2t = h1;
    for (int i = tid; i < 16384; i += 256) {   // W2t[n][k] = W2[k][n]
        int k = i >> 7, n = i & 127;
        W2t[n * SH + k] = __float2half(W2[i]);
    }
    for (int i = tid; i < 4096; i += 256) {    // W3t[n][k] = W3[k][n]
        int k = i >> 5, n = i & 31;
        W3t[n * SH + k] = __float2half(W3[i]);
    }
    if (tid < 128) { b1s[tid] = b1[tid]; b2s[tid] = b2[tid]; }
    if (tid < 32)  b3s[tid] = b3[tid];
    __syncthreads();

    // persistent W2 fragments (64 regs/lane)
    uint32_t bW2[4][16];
#pragma unroll
    for (int nt = 0; nt < 4; nt++) {
        const __half* bp = W2t + (wn12 + 8 * nt + g) * SH + 2 * t;
#pragma unroll
        for (int ks = 0; ks < 8; ks++) {
            bW2[nt][2 * ks]     = *(const uint32_t*)(bp + 16 * ks);
            bW2[nt][2 * ks + 1] = *(const uint32_t*)(bp + 16 * ks + 8);
        }
    }
    // persistent W1 fragments (K=4, padded to k8; t>=2 lanes are zero)
    uint32_t bW1[4];
#pragma unroll
    for (int nt = 0; nt < 4; nt++) {
        int n = wn12 + 8 * nt + g;
        bW1[nt] = (t < 2) ? packh2(W1[(2 * t) * 128 + n], W1[(2 * t + 1) * 128 + n]) : 0u;
    }
    // persistent FSPool weights: channel c = 4w+ci, rank r = 4*lane+j
    float wreg[4][4];
#pragma unroll
    for (int ci = 0; ci < 4; ci++) {
        int c = 4 * w + ci;
#pragma unroll
        for (int j = 0; j < 4; j++) {
            int p = 4 * lane + j;
            float pos = (float)p * (20.0f / 127.0f);
            int idx = (int)pos; if (idx > 20) idx = 20;
            float frac = pos - (float)idx;
            int idx2 = idx + 1; if (idx2 > 20) idx2 = 20;
            wreg[ci][j] = (1.0f - frac) * pw[c * 21 + idx] + frac * pw[c * 21 + idx2];
        }
    }

    // prefetch first batch into buffer 0
    {
        int b0 = blockIdx.x;
        if (tid < 128)      cp16(xraw + tid * 4, x + (size_t)b0 * 512 + tid * 4);
        else if (tid < 132) cp16(epsb + (tid - 128) * 4, eps + (size_t)b0 * 16 + (tid - 128) * 4);
    }
    asm volatile("cp.async.commit_group;\n");

    int buf = 0;
    const int grid = gridDim.x;

    for (int b = blockIdx.x; b < NB; b += grid) {
        int bn = b + grid; if (bn >= NB) bn = blockIdx.x;
        int nb = buf ^ 1;
        if (tid < 128)      cp16(xraw + nb * 512 + tid * 4, x + (size_t)bn * 512 + tid * 4);
        else if (tid < 132) cp16(epsb + nb * 16 + (tid - 128) * 4, eps + (size_t)bn * 16 + (tid - 128) * 4);
        asm volatile("cp.async.commit_group;\n");
        asm volatile("cp.async.wait_group 1;\n");
        __syncthreads();

        float acc[64];

        // ---- layer 1: h1 = relu(x @ W1 + b1), M128 N128 K4(pad8), tile 64x32 ----
#pragma unroll
        for (int i = 0; i < 64; i++) acc[i] = 0.f;
        {
            uint32_t a1[4][2];
#pragma unroll
            for (int ms = 0; ms < 4; ms++) {
                int row = wm12 + 16 * ms + g;
                if (t < 2) {
                    float2 v0 = *(const float2*)&xraw[buf * 512 + row * 4 + 2 * t];
                    float2 v1 = *(const float2*)&xraw[buf * 512 + (row + 8) * 4 + 2 * t];
                    a1[ms][0] = packh2(v0.x, v0.y);
                    a1[ms][1] = packh2(v1.x, v1.y);
                } else { a1[ms][0] = 0u; a1[ms][1] = 0u; }
            }
#pragma unroll
            for (int ms = 0; ms < 4; ms++)
#pragma unroll
                for (int nt = 0; nt < 4; nt++)
                    mma16808(&acc[(ms * 4 + nt) * 4], a1[ms], bW1[nt]);
#pragma unroll
            for (int ms = 0; ms < 4; ms++)
#pragma unroll
                for (int nt = 0; nt < 4; nt++) {
                    int r0 = wm12 + 16 * ms + g;
                    int c0 = wn12 + 8 * nt + 2 * t;
                    float* a = &acc[(ms * 4 + nt) * 4];
                    float bb0 = b1s[c0], bb1 = b1s[c0 + 1];
                    *(__half2*)(h1 + r0 * SH + c0) =
                        __floats2half2_rn(fmaxf(a[0] + bb0, 0.f), fmaxf(a[1] + bb1, 0.f));
                    *(__half2*)(h1 + (r0 + 8) * SH + c0) =
                        __floats2half2_rn(fmaxf(a[2] + bb0, 0.f), fmaxf(a[3] + bb1, 0.f));
                }
        }
        __syncthreads();

        // ---- layer 2: h2 = relu(h1 @ W2 + b2), K=128, tile 64x32, B in regs ----
#pragma unroll
        for (int i = 0; i < 64; i++) acc[i] = 0.f;
        {
            uint32_t af[2][4][4];
#pragma unroll
            for (int ms = 0; ms < 4; ms++) LDSM4(af[0][ms], aBase2 + (16 * ms * SH) * 2);
#pragma unroll
            for (int ks = 0; ks < 8; ks++) {
                if (ks < 7) {
#pragma unroll
                    for (int ms = 0; ms < 4; ms++)
                        LDSM4(af[(ks + 1) & 1][ms], aBase2 + (16 * ms * SH + 16 * (ks + 1)) * 2);
                }
#pragma unroll
                for (int ms = 0; ms < 4; ms++)
#pragma unroll
                    for (int nt = 0; nt < 4; nt++)
                        mma16816(&acc[(ms * 4 + nt) * 4], af[ks & 1][ms], &bW2[nt][2 * ks]);
            }
#pragma unroll
            for (int ms = 0; ms < 4; ms++)
#pragma unroll
                for (int nt = 0; nt < 4; nt++) {
                    int r0 = wm12 + 16 * ms + g;
                    int c0 = wn12 + 8 * nt + 2 * t;
                    float* a = &acc[(ms * 4 + nt) * 4];
                    float bb0 = b2s[c0], bb1 = b2s[c0 + 1];
                    *(__half2*)(h2 + r0 * SH + c0) =
                        __floats2half2_rn(fmaxf(a[0] + bb0, 0.f), fmaxf(a[1] + bb1, 0.f));
                    *(__half2*)(h2 + (r0 + 8) * SH + c0) =
                        __floats2half2_rn(fmaxf(a[2] + bb0, 0.f), fmaxf(a[3] + bb1, 0.f));
                }
        }
        __syncthreads();

        // ---- layer 3: z^T = h2 @ W3 + b3, N=32, tile 32x16 -> zt (channel-major fp32) ----
        {
            float acc3[16];
#pragma unroll
            for (int i = 0; i < 16; i++) acc3[i] = 0.f;
#pragma unroll
            for (int ks = 0; ks < 8; ks++) {
                uint32_t a3[2][4], bf[2][2];
#pragma unroll
                for (int ms = 0; ms < 2; ms++)
                    LDSM4(a3[ms], aBase3 + (16 * ms * SH + 16 * ks) * 2);
#pragma unroll
                for (int nt = 0; nt < 2; nt++) {
                    const __half* bp = W3t + (wn3 + 8 * nt + g) * SH + 16 * ks + 2 * t;
                    bf[nt][0] = *(const uint32_t*)(bp);
                    bf[nt][1] = *(const uint32_t*)(bp + 8);
                }
#pragma unroll
                for (int ms = 0; ms < 2; ms++)
#pragma unroll
                    for (int nt = 0; nt < 2; nt++)
                        mma16816(&acc3[(ms * 2 + nt) * 4], a3[ms], bf[nt]);
            }
#pragma unroll
            for (int ms = 0; ms < 2; ms++)
#pragma unroll
                for (int nt = 0; nt < 2; nt++) {
                    int r = wm3 + 16 * ms + g;
                    int c = wn3 + 8 * nt + 2 * t;
                    float* a = &acc3[(ms * 2 + nt) * 4];
                    zt[c * ZST + r]           = a[0] + b3s[c];
                    zt[(c + 1) * ZST + r]     = a[1] + b3s[c + 1];
                    zt[c * ZST + r + 8]       = a[2] + b3s[c];
                    zt[(c + 1) * ZST + r + 8] = a[3] + b3s[c + 1];
                }
        }
        __syncthreads();

        // ---- sort + pool: 4 channels/warp, element e = 4*lane + j ----
        {
            float v[4][4];
#pragma unroll
            for (int ci = 0; ci < 4; ci++) {
                float4 q = *(const float4*)&zt[(4 * w + ci) * ZST + 4 * lane];
                v[ci][0] = q.x; v[ci][1] = q.y; v[ci][2] = q.z; v[ci][3] = q.w;
            }
            // k=2
#pragma unroll
            for (int ci = 0; ci < 4; ci++) { CEX(v[ci][0], v[ci][1], true); CEX(v[ci][2], v[ci][3], false); }
            // k=4
            {
                const bool dsc = (lane & 1) == 0;
#pragma unroll
                for (int ci = 0; ci < 4; ci++) { CEX(v[ci][0], v[ci][2], dsc); CEX(v[ci][1], v[ci][3], dsc); }
#pragma unroll
                for (int ci = 0; ci < 4; ci++) { CEX(v[ci][0], v[ci][1], dsc); CEX(v[ci][2], v[ci][3], dsc); }
            }
            // k = 8..128
#pragma unroll
            for (int kk = 8; kk <= 128; kk <<= 1) {
                const bool dsc = (lane & (kk >> 2)) == 0;
#pragma unroll
                for (int d = kk >> 1; d >= 4; d >>= 1) {
                    const bool keep = dsc == ((lane & (d >> 2)) == 0);
#pragma unroll
                    for (int ci = 0; ci < 4; ci++)
#pragma unroll
                        for (int j = 0; j < 4; j++) {
                            float p = __shfl_xor_sync(0xffffffffu, v[ci][j], d >> 2);
                            v[ci][j] = keep ? fmaxf(v[ci][j], p) : fminf(v[ci][j], p);
                        }
                }
#pragma unroll
                for (int ci = 0; ci < 4; ci++) { CEX(v[ci][0], v[ci][2], dsc); CEX(v[ci][1], v[ci][3], dsc); }
#pragma unroll
                for (int ci = 0; ci < 4; ci++) { CEX(v[ci][0], v[ci][1], dsc); CEX(v[ci][2], v[ci][3], dsc); }
            }
            // weighted pool (rank r = 4*lane+j matches wreg layout)
            float s[4];
#pragma unroll
            for (int ci = 0; ci < 4; ci++)
                s[ci] = v[ci][0] * wreg[ci][0] + v[ci][1] * wreg[ci][1] +
                        v[ci][2] * wreg[ci][2] + v[ci][3] * wreg[ci][3];
#pragma unroll
            for (int off = 16; off > 0; off >>= 1)
#pragma unroll
                for (int ci = 0; ci < 4; ci++)
                    s[ci] += __shfl_xor_sync(0xffffffffu, s[ci], off);
            if (lane == 0) {
#pragma unroll
                for (int ci = 0; ci < 4; ci++) pooled[4 * w + ci] = s[ci];
            }
        }
        __syncthreads();

        // ---- outputs (mus | logvars | samples) ----
        if (tid < 16) {
            const int l = tid;
            float mu = pooled[2 * l];
            float lv = pooled[2 * l + 1];
            float ev = epsb[buf * 16 + l];
            float sp = mu + ev * expf(0.5f * lv);
            out[(size_t)b * 16 + l]                       = mu;
            out[(size_t)NB * 16 + (size_t)b * 16 + l]     = lv;
            out[(size_t)2 * NB * 16 + (size_t)b * 16 + l] = sp;
        }
        buf ^= 1;
    }
}

extern "C" void kernel_launch(void* const* d_in, const int* in_sizes, int n_in,
                              void* d_out, int out_size) {
    const float* x   = (const float*)d_in[0];
    const float* W1  = (const float*)d_in[1];
    const float* b1  = (const float*)d_in[2];
    const float* W2  = (const float*)d_in[3];
    const float* b2  = (const float*)d_in[4];
    const float* W3  = (const float*)d_in[5];
    const float* b3  = (const float*)d_in[6];
    const float* pw  = (const float*)d_in[7];
    const float* eps = (const float*)d_in[8];
    float* out = (float*)d_out;

    int dev = 0;
    cudaGetDevice(&dev);
    int nsm = 148;
    cudaDeviceGetAttribute(&nsm, cudaDevAttrMultiProcessorCount, dev);
    cudaFuncSetAttribute(enc_kernel, cudaFuncAttributeMaxDynamicSharedMemorySize, SMEM_BYTES);
    enc_kernel<<<nsm, 256, SMEM_BYTES>>>(x, W1, b1, W2, b2, W3, b3, pw, eps, out);
}

// round 3
// speedup vs baseline: 1.4420x; 1.1482x over previous
#include <cuda_runtime.h>
#include <cuda_fp16.h>
#include <cstdint>

#define NB    8192
#define SH    136    // padded half stride for h1/h2/W2t/W3t rows (68 words -> conflict-free)
#define ZSTH  136    // padded half2 stride for zth pair-rows (544B, 16B aligned)

// shared memory byte offsets (16B aligned)
#define OFF_XRAW   0        // 2*512*4 = 4096
#define OFF_EPS    4096     // 2*16*4  = 128
#define OFF_B1     4224     // 512
#define OFF_B2     4736     // 512
#define OFF_B3     5248     // 128
#define OFF_POOLED 5376     // 128
#define OFF_W3T    5504     // 32*136*2 = 8704
#define OFF_H1     14208    // 128*136*2 = 34816   (W2 staged here in prologue)
#define OFF_H2     49024    // 128*136*2 = 34816
#define OFF_ZTH    83840    // 16*136*4 = 8704     (half2 channel pairs)
#define SMEM_BYTES 92544

__device__ __forceinline__ void mma16816(float* d, const uint32_t* a, const uint32_t* b) {
    asm volatile(
        "mma.sync.aligned.m16n8k16.row.col.f32.f16.f16.f32 "
        "{%0,%1,%2,%3},{%4,%5,%6,%7},{%8,%9},{%0,%1,%2,%3};\n"
        : "+f"(d[0]), "+f"(d[1]), "+f"(d[2]), "+f"(d[3])
        : "r"(a[0]), "r"(a[1]), "r"(a[2]), "r"(a[3]), "r"(b[0]), "r"(b[1]));
}

__device__ __forceinline__ void mma16808(float* d, const uint32_t* a, uint32_t b) {
    asm volatile(
        "mma.sync.aligned.m16n8k8.row.col.f32.f16.f16.f32 "
        "{%0,%1,%2,%3},{%4,%5},{%6},{%0,%1,%2,%3};\n"
        : "+f"(d[0]), "+f"(d[1]), "+f"(d[2]), "+f"(d[3])
        : "r"(a[0]), "r"(a[1]), "r"(b));
}

#define LDSM4(r, addr) \
    asm volatile("ldmatrix.sync.aligned.m8n8.x4.shared.b16 {%0,%1,%2,%3}, [%4];" \
                 : "=r"((r)[0]), "=r"((r)[1]), "=r"((r)[2]), "=r"((r)[3]) : "r"(addr))

#define STSM4(addr, r0, r1, r2, r3) \
    asm volatile("stmatrix.sync.aligned.m8n8.x4.shared.b16 [%0], {%1,%2,%3,%4};" \
                 :: "r"(addr), "r"(r0), "r"(r1), "r"(r2), "r"(r3))

__device__ __forceinline__ void cp16(void* s, const void* g) {
    uint32_t sa = (uint32_t)__cvta_generic_to_shared(s);
    asm volatile("cp.async.ca.shared.global [%0], [%1], 16;\n" :: "r"(sa), "l"(g));
}

__device__ __forceinline__ uint32_t packh2(float a, float b) {
    __half2 h = __floats2half2_rn(a, b);
    return *(uint32_t*)&h;
}

__device__ __forceinline__ uint32_t h2max(uint32_t a, uint32_t b) {
    __half2 r = __hmax2(*(__half2*)&a, *(__half2*)&b);
    return *(uint32_t*)&r;
}
__device__ __forceinline__ uint32_t h2min(uint32_t a, uint32_t b) {
    __half2 r = __hmin2(*(__half2*)&a, *(__half2*)&b);
    return *(uint32_t*)&r;
}

#define CEXH(a, b, dsc) do { uint32_t _hi = h2max(a, b), _lo = h2min(a, b); \
                             (a) = (dsc) ? _hi : _lo; (b) = (dsc) ? _lo : _hi; } while (0)

__global__ void __launch_bounds__(256, 1)
enc_kernel(const float* __restrict__ x,  const float* __restrict__ W1,
           const float* __restrict__ b1, const float* __restrict__ W2,
           const float* __restrict__ b2, const float* __restrict__ W3,
           const float* __restrict__ b3, const float* __restrict__ pw,
           const float* __restrict__ eps, float* __restrict__ out) {
    extern __shared__ char smem[];
    float*    xraw  = (float*)(smem + OFF_XRAW);
    float*    epsb  = (float*)(smem + OFF_EPS);
    float*    b1s   = (float*)(smem + OFF_B1);
    float*    b2s   = (float*)(smem + OFF_B2);
    float*    b3s   = (float*)(smem + OFF_B3);
    float*    pooled= (float*)(smem + OFF_POOLED);
    __half*   W3t   = (__half*)(smem + OFF_W3T);
    __half*   h1    = (__half*)(smem + OFF_H1);
    __half*   h2    = (__half*)(smem + OFF_H2);
    uint32_t* zth   = (uint32_t*)(smem + OFF_ZTH);   // half2, pair-row stride ZSTH

    const int tid  = threadIdx.x;
    const int w    = tid >> 5;
    const int lane = tid & 31;
    const int g    = lane >> 2, t = lane & 3;

    // warp tiles
    const int wm12 = (w & 1) * 64, wn12 = (w >> 1) * 32;   // layers 1,2: 64x32
    const int wm3  = (w & 3) * 32, wn3  = (w >> 2) * 16;   // layer 3: 32x16

    // ldmatrix lane address components
    const int mi    = lane >> 3;
    const int arow  = (mi & 1) * 8 + (lane & 7);
    const int acol  = (mi >> 1) * 8;
    // stmatrix lane address components (m0: r+0..7/c+0..7, m1: r+8/c, m2: r/c+8, m3: r+8/c+8)
    const int srow  = (mi & 1) * 8 + (lane & 7);
    const int scol  = (mi >> 1) * 8;

    const uint32_t smem_u32 = (uint32_t)__cvta_generic_to_shared(smem);
    const uint32_t aBase2 = smem_u32 + OFF_H1 + ((wm12 + arow) * SH + acol) * 2;
    const uint32_t aBase3 = smem_u32 + OFF_H2 + ((wm3  + arow) * SH + acol) * 2;
    const uint32_t sBase1 = smem_u32 + OFF_H1 + ((wm12 + srow) * SH + wn12 + scol) * 2;
    const uint32_t sBase2 = smem_u32 + OFF_H2 + ((wm12 + srow) * SH + wn12 + scol) * 2;

    // ---------------- prologue ----------------
    __half* W2t = h1;  // stage W2 in h1 region, consumed into registers below
    for (int i = tid; i < 16384; i += 256) {   // W2t[n][k] = W2[k][n]
        int k = i >> 7, n = i & 127;
        W2t[n * SH + k] = __float2half(W2[i]);
    }
    for (int i = tid; i < 4096; i += 256) {    // W3t[n][k] = W3[k][n]
        int k = i >> 5, n = i & 31;
        W3t[n * SH + k] = __float2half(W3[i]);
    }
    if (tid < 128) { b1s[tid] = b1[tid]; b2s[tid] = b2[tid]; }
    if (tid < 32)  b3s[tid] = b3[tid];
    __syncthreads();

    // persistent W2 fragments (64 regs/lane)
    uint32_t bW2[4][16];
#pragma unroll
    for (int nt = 0; nt < 4; nt++) {
        const __half* bp = W2t + (wn12 + 8 * nt + g) * SH + 2 * t;
#pragma unroll
        for (int ks = 0; ks < 8; ks++) {
            bW2[nt][2 * ks]     = *(const uint32_t*)(bp + 16 * ks);
            bW2[nt][2 * ks + 1] = *(const uint32_t*)(bp + 16 * ks + 8);
        }
    }
    // persistent W1 fragments
    uint32_t bW1[4];
#pragma unroll
    for (int nt = 0; nt < 4; nt++) {
        int n = wn12 + 8 * nt + g;
        bW1[nt] = (t < 2) ? packh2(W1[(2 * t) * 128 + n], W1[(2 * t + 1) * 128 + n]) : 0u;
    }
    // persistent FSPool weights: warp handles channel pairs pr=2w+ci -> channels (2pr, 2pr+1)
    float wlo[2][4], whi[2][4];
#pragma unroll
    for (int ci = 0; ci < 2; ci++) {
        int c0 = 4 * w + 2 * ci;
#pragma unroll
        for (int j = 0; j < 4; j++) {
            int p = 4 * lane + j;
            float pos = (float)p * (20.0f / 127.0f);
            int idx = (int)pos; if (idx > 20) idx = 20;
            float frac = pos - (float)idx;
            int idx2 = idx + 1; if (idx2 > 20) idx2 = 20;
            wlo[ci][j] = (1.0f - frac) * pw[c0 * 21 + idx]       + frac * pw[c0 * 21 + idx2];
            whi[ci][j] = (1.0f - frac) * pw[(c0 + 1) * 21 + idx] + frac * pw[(c0 + 1) * 21 + idx2];
        }
    }

    // prefetch first batch
    {
        int b0 = blockIdx.x;
        if (tid < 128)      cp16(xraw + tid * 4, x + (size_t)b0 * 512 + tid * 4);
        else if (tid < 132) cp16(epsb + (tid - 128) * 4, eps + (size_t)b0 * 16 + (tid - 128) * 4);
    }
    asm volatile("cp.async.commit_group;\n");

    int buf = 0;
    const int grid = gridDim.x;

    for (int b = blockIdx.x; b < NB; b += grid) {
        int bn = b + grid; if (bn >= NB) bn = blockIdx.x;
        int nb = buf ^ 1;
        if (tid < 128)      cp16(xraw + nb * 512 + tid * 4, x + (size_t)bn * 512 + tid * 4);
        else if (tid < 132) cp16(epsb + nb * 16 + (tid - 128) * 4, eps + (size_t)bn * 16 + (tid - 128) * 4);
        asm volatile("cp.async.commit_group;\n");
        asm volatile("cp.async.wait_group 1;\n");
        __syncthreads();

        float acc[64];

        // ---- layer 1: h1 = relu(x @ W1 + b1), tile 64x32 ----
#pragma unroll
        for (int i = 0; i < 64; i++) acc[i] = 0.f;
        {
            uint32_t a1[4][2];
#pragma unroll
            for (int ms = 0; ms < 4; ms++) {
                int row = wm12 + 16 * ms + g;
                if (t < 2) {
                    float2 v0 = *(const float2*)&xraw[buf * 512 + row * 4 + 2 * t];
                    float2 v1 = *(const float2*)&xraw[buf * 512 + (row + 8) * 4 + 2 * t];
                    a1[ms][0] = packh2(v0.x, v0.y);
                    a1[ms][1] = packh2(v1.x, v1.y);
                } else { a1[ms][0] = 0u; a1[ms][1] = 0u; }
            }
#pragma unroll
            for (int ms = 0; ms < 4; ms++)
#pragma unroll
                for (int nt = 0; nt < 4; nt++)
                    mma16808(&acc[(ms * 4 + nt) * 4], a1[ms], bW1[nt]);
            // epilogue via stmatrix: per (ms, col-half nh) one STSM.x4
#pragma unroll
            for (int ms = 0; ms < 4; ms++)
#pragma unroll
                for (int nh = 0; nh < 2; nh++) {
                    int c0 = wn12 + 16 * nh + 2 * t;
                    float bb0 = b1s[c0], bb1 = b1s[c0 + 1];
                    float bb2 = b1s[c0 + 8], bb3 = b1s[c0 + 9];
                    float* aA = &acc[(ms * 4 + 2 * nh) * 4];
                    float* aB = &acc[(ms * 4 + 2 * nh + 1) * 4];
                    uint32_t p0 = packh2(fmaxf(aA[0] + bb0, 0.f), fmaxf(aA[1] + bb1, 0.f));
                    uint32_t p1 = packh2(fmaxf(aA[2] + bb0, 0.f), fmaxf(aA[3] + bb1, 0.f));
                    uint32_t p2 = packh2(fmaxf(aB[0] + bb2, 0.f), fmaxf(aB[1] + bb3, 0.f));
                    uint32_t p3 = packh2(fmaxf(aB[2] + bb2, 0.f), fmaxf(aB[3] + bb3, 0.f));
                    STSM4(sBase1 + (16 * ms * SH + 16 * nh) * 2, p0, p1, p2, p3);
                }
        }
        __syncthreads();

        // ---- layer 2: h2 = relu(h1 @ W2 + b2), K=128, B in regs ----
#pragma unroll
        for (int i = 0; i < 64; i++) acc[i] = 0.f;
        {
            uint32_t af[2][4][4];
#pragma unroll
            for (int ms = 0; ms < 4; ms++) LDSM4(af[0][ms], aBase2 + (16 * ms * SH) * 2);
#pragma unroll
            for (int ks = 0; ks < 8; ks++) {
                if (ks < 7) {
#pragma unroll
                    for (int ms = 0; ms < 4; ms++)
                        LDSM4(af[(ks + 1) & 1][ms], aBase2 + (16 * ms * SH + 16 * (ks + 1)) * 2);
                }
#pragma unroll
                for (int ms = 0; ms < 4; ms++)
#pragma unroll
                    for (int nt = 0; nt < 4; nt++)
                        mma16816(&acc[(ms * 4 + nt) * 4], af[ks & 1][ms], &bW2[nt][2 * ks]);
            }
#pragma unroll
            for (int ms = 0; ms < 4; ms++)
#pragma unroll
                for (int nh = 0; nh < 2; nh++) {
                    int c0 = wn12 + 16 * nh + 2 * t;
                    float bb0 = b2s[c0], bb1 = b2s[c0 + 1];
                    float bb2 = b2s[c0 + 8], bb3 = b2s[c0 + 9];
                    float* aA = &acc[(ms * 4 + 2 * nh) * 4];
                    float* aB = &acc[(ms * 4 + 2 * nh + 1) * 4];
                    uint32_t p0 = packh2(fmaxf(aA[0] + bb0, 0.f), fmaxf(aA[1] + bb1, 0.f));
                    uint32_t p1 = packh2(fmaxf(aA[2] + bb0, 0.f), fmaxf(aA[3] + bb1, 0.f));
                    uint32_t p2 = packh2(fmaxf(aB[0] + bb2, 0.f), fmaxf(aB[1] + bb3, 0.f));
                    uint32_t p3 = packh2(fmaxf(aB[2] + bb2, 0.f), fmaxf(aB[3] + bb3, 0.f));
                    STSM4(sBase2 + (16 * ms * SH + 16 * nh) * 2, p0, p1, p2, p3);
                }
        }
        __syncthreads();

        // ---- layer 3: z^T = h2 @ W3 + b3, tile 32x16 -> zth (half2 channel pairs) ----
        {
            float acc3[16];
#pragma unroll
            for (int i = 0; i < 16; i++) acc3[i] = 0.f;
#pragma unroll
            for (int ks = 0; ks < 8; ks++) {
                uint32_t a3[2][4], bf[2][2];
#pragma unroll
                for (int ms = 0; ms < 2; ms++)
                    LDSM4(a3[ms], aBase3 + (16 * ms * SH + 16 * ks) * 2);
#pragma unroll
                for (int nt = 0; nt < 2; nt++) {
                    const __half* bp = W3t + (wn3 + 8 * nt + g) * SH + 16 * ks + 2 * t;
                    bf[nt][0] = *(const uint32_t*)(bp);
                    bf[nt][1] = *(const uint32_t*)(bp + 8);
                }
#pragma unroll
                for (int ms = 0; ms < 2; ms++)
#pragma unroll
                    for (int nt = 0; nt < 2; nt++)
                        mma16816(&acc3[(ms * 2 + nt) * 4], a3[ms], bf[nt]);
            }
#pragma unroll
            for (int ms = 0; ms < 2; ms++)
#pragma unroll
                for (int nt = 0; nt < 2; nt++) {
                    int r  = wm3 + 16 * ms + g;
                    int c  = wn3 + 8 * nt + 2 * t;
                    int cp = c >> 1;   // channel-pair row
                    float* a = &acc3[(ms * 2 + nt) * 4];
                    float bb0 = b3s[c], bb1 = b3s[c + 1];
                    zth[cp * ZSTH + r]     = packh2(a[0] + bb0, a[1] + bb1);
                    zth[cp * ZSTH + r + 8] = packh2(a[2] + bb0, a[3] + bb1);
                }
        }
        __syncthreads();

        // ---- sort + pool: 2 half2 streams/warp (4 channels), element e = 4*lane + j ----
        {
            uint32_t v[2][4];
#pragma unroll
            for (int ci = 0; ci < 2; ci++) {
                uint4 q = *(const uint4*)&zth[(2 * w + ci) * ZSTH + 4 * lane];
                v[ci][0] = q.x; v[ci][1] = q.y; v[ci][2] = q.z; v[ci][3] = q.w;
            }
            // k=2
#pragma unroll
            for (int ci = 0; ci < 2; ci++) { CEXH(v[ci][0], v[ci][1], true); CEXH(v[ci][2], v[ci][3], false); }
            // k=4
            {
                const bool dsc = (lane & 1) == 0;
#pragma unroll
                for (int ci = 0; ci < 2; ci++) { CEXH(v[ci][0], v[ci][2], dsc); CEXH(v[ci][1], v[ci][3], dsc); }
#pragma unroll
                for (int ci = 0; ci < 2; ci++) { CEXH(v[ci][0], v[ci][1], dsc); CEXH(v[ci][2], v[ci][3], dsc); }
            }
            // k = 8..128
#pragma unroll
            for (int kk = 8; kk <= 128; kk <<= 1) {
                const bool dsc = (lane & (kk >> 2)) == 0;
#pragma unroll
                for (int d = kk >> 1; d >= 4; d >>= 1) {
                    const bool keep = dsc == ((lane & (d >> 2)) == 0);
#pragma unroll
                    for (int ci = 0; ci < 2; ci++)
#pragma unroll
                        for (int j = 0; j < 4; j++) {
                            uint32_t p = __shfl_xor_sync(0xffffffffu, v[ci][j], d >> 2);
                            v[ci][j] = keep ? h2max(v[ci][j], p) : h2min(v[ci][j], p);
                        }
                }
#pragma unroll
                for (int ci = 0; ci < 2; ci++) { CEXH(v[ci][0], v[ci][2], dsc); CEXH(v[ci][1], v[ci][3], dsc); }
#pragma unroll
                for (int ci = 0; ci < 2; ci++) { CEXH(v[ci][0], v[ci][1], dsc); CEXH(v[ci][2], v[ci][3], dsc); }
            }
            // weighted pool (rank r = 4*lane+j); fp32 accumulate
            float s[4];
#pragma unroll
            for (int ci = 0; ci < 2; ci++) {
                float slo = 0.f, shi = 0.f;
#pragma unroll
                for (int j = 0; j < 4; j++) {
                    float2 f = __half22float2(*(__half2*)&v[ci][j]);
                    slo += f.x * wlo[ci][j];
                    shi += f.y * whi[ci][j];
                }
                s[2 * ci] = slo; s[2 * ci + 1] = shi;
            }
#pragma unroll
            for (int off = 16; off > 0; off >>= 1)
#pragma unroll
                for (int i = 0; i < 4; i++)
                    s[i] += __shfl_xor_sync(0xffffffffu, s[i], off);
            if (lane == 0) {
#pragma unroll
                for (int i = 0; i < 4; i++) pooled[4 * w + i] = s[i];
            }
        }
        __syncthreads();

        // ---- outputs (mus | logvars | samples) ----
        if (tid < 16) {
            const int l = tid;
            float mu = pooled[2 * l];
            float lv = pooled[2 * l + 1];
            float ev = epsb[buf * 16 + l];
            float sp = mu + ev * expf(0.5f * lv);
            out[(size_t)b * 16 + l]                       = mu;
            out[(size_t)NB * 16 + (size_t)b * 16 + l]     = lv;
            out[(size_t)2 * NB * 16 + (size_t)b * 16 + l] = sp;
        }
        buf ^= 1;
    }
}

extern "C" void kernel_launch(void* const* d_in, const int* in_sizes, int n_in,
                              void* d_out, int out_size) {
    const float* x   = (const float*)d_in[0];
    const float* W1  = (const float*)d_in[1];
    const float* b1  = (const float*)d_in[2];
    const float* W2  = (const float*)d_in[3];
    const float* b2  = (const float*)d_in[4];
    const float* W3  = (const float*)d_in[5];
    const float* b3  = (const float*)d_in[6];
    const float* pw  = (const float*)d_in[7];
    const float* eps = (const float*)d_in[8];
    float* out = (float*)d_out;

    int dev = 0;
    cudaGetDevice(&dev);
    int nsm = 148;
    cudaDeviceGetAttribute(&nsm, cudaDevAttrMultiProcessorCount, dev);
    cudaFuncSetAttribute(enc_kernel, cudaFuncAttributeMaxDynamicSharedMemorySize, SMEM_BYTES);
    enc_kernel<<<nsm, 256, SMEM_BYTES>>>(x, W1, b1, W2, b2, W3, b3, pw, eps, out);
}